// round 3
// baseline (speedup 1.0000x reference)
#include <cuda_runtime.h>

#define NN    100000
#define EEMAX 3200000
#define F1    16
#define F2    40
#define DIN   512

// Scratch (static device globals — no allocation allowed)
__device__ int   g_cnt [NN];        // edge in-degree (without self-loop)
__device__ int   g_off [NN];        // CSR offsets (exclusive scan of cnt)
__device__ int   g_cur [NN];        // fill cursors
__device__ int   g_adj [EEMAX];     // CSR: source node per slot
__device__ int   g_bsum[128];       // scan block sums
__device__ float g_dinv[NN];
__device__ float g_src [NN * F1];   // dinv * (x @ W1)
__device__ float g_hds [NN * F1];   // dinv * dropout(h + b1)

// ---------------------------------------------------------------------------
__global__ void k_zero() {
    int v = blockIdx.x * blockDim.x + threadIdx.x;
    if (v < NN) g_cnt[v] = 0;
}

__global__ void k_count(const int* __restrict__ col, int E) {
    int e = blockIdx.x * blockDim.x + threadIdx.x;
    if (e < E) atomicAdd(&g_cnt[col[e]], 1);
}

// ---------------------------------------------------------------------------
// Two-level exclusive scan of g_cnt -> g_off
__global__ __launch_bounds__(1024) void k_scan1() {
    __shared__ int wsum[32];
    int i = blockIdx.x * 1024 + threadIdx.x;
    int v = (i < NN) ? g_cnt[i] : 0;
    int lane = threadIdx.x & 31, wid = threadIdx.x >> 5;
    int x = v;
#pragma unroll
    for (int d = 1; d < 32; d <<= 1) {
        int y = __shfl_up_sync(0xffffffffu, x, d);
        if (lane >= d) x += y;
    }
    if (lane == 31) wsum[wid] = x;
    __syncthreads();
    if (wid == 0) {
        int w = wsum[lane];
#pragma unroll
        for (int d = 1; d < 32; d <<= 1) {
            int y = __shfl_up_sync(0xffffffffu, w, d);
            if (lane >= d) w += y;
        }
        wsum[lane] = w;
    }
    __syncthreads();
    int incl = x + (wid > 0 ? wsum[wid - 1] : 0);
    if (i < NN) g_off[i] = incl - v;               // block-local exclusive
    if (threadIdx.x == 1023) g_bsum[blockIdx.x] = incl;
}

// parallel exclusive scan of up to 128 block sums (Hillis-Steele)
__global__ void k_scan2(int nb) {
    __shared__ int s[128];
    int t = threadIdx.x;
    int v = (t < nb) ? g_bsum[t] : 0;
    s[t] = v;
    __syncthreads();
#pragma unroll
    for (int d = 1; d < 128; d <<= 1) {
        int y = (t >= d) ? s[t - d] : 0;
        __syncthreads();
        s[t] += y;
        __syncthreads();
    }
    if (t < nb) g_bsum[t] = s[t] - v;              // exclusive
}

__global__ void k_scan3() {
    int i = blockIdx.x * blockDim.x + threadIdx.x;
    if (i < NN) {
        int o = g_off[i] + g_bsum[i >> 10];
        g_off[i] = o;
        g_cur[i] = o;
    }
}

// ---------------------------------------------------------------------------
__global__ void k_fill(const int* __restrict__ row, const int* __restrict__ col, int E) {
    int e = blockIdx.x * blockDim.x + threadIdx.x;
    if (e >= E) return;
    int c = col[e];
    int pos = atomicAdd(&g_cur[c], 1);
    g_adj[pos] = row[e];
}

// ---------------------------------------------------------------------------
// xw = x @ W1 ; dinv = rsqrt(cnt+1) ; g_src = dinv * xw
// Depends ONLY on g_cnt (runs concurrently with scan/fill on a side stream).
__global__ __launch_bounds__(256) void k_gemm1(const float* __restrict__ x,
                                               const float* __restrict__ W1) {
    __shared__ float4 sW[DIN * 4];               // W1[512][16] as float4[512][4]
    const float4* Wv = (const float4*)W1;
    for (int i = threadIdx.x; i < DIN * 4; i += 256) sW[i] = Wv[i];
    __syncthreads();

    int v = blockIdx.x * 256 + threadIdx.x;
    if (v >= NN) return;

    float acc[16];
#pragma unroll
    for (int i = 0; i < 16; ++i) acc[i] = 0.0f;

    const float4* xr = (const float4*)(x + (size_t)v * DIN);
#pragma unroll 4
    for (int j = 0; j < DIN / 4; ++j) {
        float4 xv = xr[j];
#pragma unroll
        for (int u = 0; u < 4; ++u) {
            float xs = (u == 0) ? xv.x : (u == 1) ? xv.y : (u == 2) ? xv.z : xv.w;
            int k = j * 4 + u;
#pragma unroll
            for (int q = 0; q < 4; ++q) {
                float4 w = sW[k * 4 + q];
                acc[q * 4 + 0] += xs * w.x;
                acc[q * 4 + 1] += xs * w.y;
                acc[q * 4 + 2] += xs * w.z;
                acc[q * 4 + 3] += xs * w.w;
            }
        }
    }

    float d = rsqrtf((float)(g_cnt[v] + 1));      // +1 self-loop
    g_dinv[v] = d;
    float4* sv = (float4*)(g_src + (size_t)v * F1);
#pragma unroll
    for (int q = 0; q < 4; ++q)
        sv[q] = make_float4(d * acc[q*4], d * acc[q*4+1], d * acc[q*4+2], d * acc[q*4+3]);
}

// ---------------------------------------------------------------------------
// JAX threefry2x32 (partitionable): key=(0,42), ctr=(0, idx).
// bernoulli(0.5) keep  <=>  MSB(out0 ^ out1) == 0
__device__ __forceinline__ unsigned tf_keep_bits(unsigned idx) {
    const unsigned k0 = 0u, k1 = 42u, k2 = 0u ^ 42u ^ 0x1BD11BDAu;
    unsigned x0 = k0;
    unsigned x1 = idx + k1;
#define TFR(r) { x0 += x1; x1 = (x1 << (r)) | (x1 >> (32 - (r))); x1 ^= x0; }
    TFR(13) TFR(15) TFR(26) TFR(6)   x0 += k1; x1 += k2 + 1u;
    TFR(17) TFR(29) TFR(16) TFR(24)  x0 += k2; x1 += k0 + 2u;
    TFR(13) TFR(15) TFR(26) TFR(6)   x0 += k0; x1 += k1 + 3u;
    TFR(17) TFR(29) TFR(16) TFR(24)  x0 += k1; x1 += k2 + 4u;
    TFR(13) TFR(15) TFR(26) TFR(6)   x0 += k2; x1 += k0 + 5u;
#undef TFR
    return x0 ^ x1;
}

// ---------------------------------------------------------------------------
// Layer-1 aggregation: ONE WARP PER NODE (uniform loop bound -> no divergence).
// lane = es*4 + q : es in [0,8) = edge slot, q in [0,4) = float4 of 16 feats.
// g_hds[t] = dinv[t] * dropout( dinv[t]*(self + sum) + b1 )
__global__ __launch_bounds__(256) void k_agg1(const float* __restrict__ b1) {
    int t = blockIdx.x * 8 + (threadIdx.x >> 5);
    if (t >= NN) return;
    int lane = threadIdx.x & 31;
    int q = lane & 3, es = lane >> 2;

    int beg = g_off[t], end = beg + g_cnt[t];
    const float4* src = (const float4*)g_src;

    float4 acc = make_float4(0.f, 0.f, 0.f, 0.f);
    for (int pos = beg + es; pos < end; pos += 8) {
        int r = g_adj[pos];
        float4 s = src[r * 4 + q];
        acc.x += s.x; acc.y += s.y; acc.z += s.z; acc.w += s.w;
    }
    // reduce across edge slots (bits 2..4 of lane); q (bits 0..1) preserved
#pragma unroll
    for (int d = 16; d >= 4; d >>= 1) {
        acc.x += __shfl_xor_sync(0xffffffffu, acc.x, d);
        acc.y += __shfl_xor_sync(0xffffffffu, acc.y, d);
        acc.z += __shfl_xor_sync(0xffffffffu, acc.z, d);
        acc.w += __shfl_xor_sync(0xffffffffu, acc.w, d);
    }

    if (es == 0) {
        float4 self = src[t * 4 + q];
        acc.x += self.x; acc.y += self.y; acc.z += self.z; acc.w += self.w;
        float d = g_dinv[t];
        float4 bb = ((const float4*)b1)[q];
        unsigned idx = (unsigned)(t * 16 + q * 4);
        float h0 = d * acc.x + bb.x, h1 = d * acc.y + bb.y;
        float h2 = d * acc.z + bb.z, h3 = d * acc.w + bb.w;
        float o0 = (tf_keep_bits(idx + 0) & 0x80000000u) ? 0.0f : 2.0f * d * h0;
        float o1 = (tf_keep_bits(idx + 1) & 0x80000000u) ? 0.0f : 2.0f * d * h1;
        float o2 = (tf_keep_bits(idx + 2) & 0x80000000u) ? 0.0f : 2.0f * d * h2;
        float o3 = (tf_keep_bits(idx + 3) & 0x80000000u) ? 0.0f : 2.0f * d * h3;
        ((float4*)g_hds)[t * 4 + q] = make_float4(o0, o1, o2, o3);
    }
}

// ---------------------------------------------------------------------------
// Layer-2 aggregation + fused (16x40 GEMM + b2), one warp per node.
__global__ __launch_bounds__(256) void k_agg2(const float* __restrict__ W2,
                                              const float* __restrict__ b2,
                                              float* __restrict__ out) {
    __shared__ float sW[F1 * F2];
    __shared__ float sb[F2];
    for (int i = threadIdx.x; i < F1 * F2; i += 256) sW[i] = W2[i];
    if (threadIdx.x < F2) sb[threadIdx.x] = b2[threadIdx.x];
    __syncthreads();

    int t = blockIdx.x * 8 + (threadIdx.x >> 5);
    if (t >= NN) return;
    int lane = threadIdx.x & 31;
    int q = lane & 3, es = lane >> 2;

    int beg = g_off[t], end = beg + g_cnt[t];
    const float4* src = (const float4*)g_hds;

    float4 acc = make_float4(0.f, 0.f, 0.f, 0.f);
    for (int pos = beg + es; pos < end; pos += 8) {
        int r = g_adj[pos];
        float4 s = src[r * 4 + q];
        acc.x += s.x; acc.y += s.y; acc.z += s.z; acc.w += s.w;
    }
#pragma unroll
    for (int d = 16; d >= 4; d >>= 1) {
        acc.x += __shfl_xor_sync(0xffffffffu, acc.x, d);
        acc.y += __shfl_xor_sync(0xffffffffu, acc.y, d);
        acc.z += __shfl_xor_sync(0xffffffffu, acc.z, d);
        acc.w += __shfl_xor_sync(0xffffffffu, acc.w, d);
    }
    // all lanes now hold the full edge-sum for their q; add self + scale
    float4 self = src[t * 4 + q];
    float d = g_dinv[t];
    acc.x = d * (acc.x + self.x);
    acc.y = d * (acc.y + self.y);
    acc.z = d * (acc.z + self.z);
    acc.w = d * (acc.w + self.w);

    // assemble all 16 features into every lane (width-4 shuffles)
    float gg[16];
#pragma unroll
    for (int s = 0; s < 4; ++s) {
        gg[s*4+0] = __shfl_sync(0xffffffffu, acc.x, s, 4);
        gg[s*4+1] = __shfl_sync(0xffffffffu, acc.y, s, 4);
        gg[s*4+2] = __shfl_sync(0xffffffffu, acc.z, s, 4);
        gg[s*4+3] = __shfl_sync(0xffffffffu, acc.w, s, 4);
    }

    // lanes 0..9 each compute 4 of the 40 outputs and store one float4
    if (lane < 10) {
        int f0 = lane * 4;
        float o0 = sb[f0], o1 = sb[f0+1], o2 = sb[f0+2], o3 = sb[f0+3];
#pragma unroll
        for (int k = 0; k < F1; ++k) {
            float gv = gg[k];
            const float* wr = sW + k * F2 + f0;
            o0 += gv * wr[0]; o1 += gv * wr[1];
            o2 += gv * wr[2]; o3 += gv * wr[3];
        }
        ((float4*)(out + (size_t)t * F2))[lane] = make_float4(o0, o1, o2, o3);
    }
}

// ---------------------------------------------------------------------------
extern "C" void kernel_launch(void* const* d_in, const int* in_sizes, int n_in,
                              void* d_out, int out_size) {
    const float* x  = (const float*)d_in[0];
    const int*   ei = (const int*)  d_in[1];
    const float* W1 = (const float*)d_in[2];
    const float* b1 = (const float*)d_in[3];
    const float* W2 = (const float*)d_in[4];
    const float* b2 = (const float*)d_in[5];
    float* out = (float*)d_out;

    int E = in_sizes[1] / 2;                  // 3,200,000
    if (E > EEMAX) E = EEMAX;
    const int* row = ei;
    const int* col = ei + E;

    const int TB = 256;
    int nb_n = (NN + TB - 1) / TB;
    int nb_e = (E + TB - 1) / TB;
    int nb_s = (NN + 1023) / 1024;            // scan blocks (98)
    int nb_a = (NN + 7) / 8;                  // agg blocks (1 warp/node)

    // side stream + events for fork/join inside graph capture
    // (host-side objects only; intentionally not destroyed — capture holds them,
    //  and kernel_launch is invoked only a handful of times outside the timed replay)
    cudaStream_t sB;
    cudaEvent_t evFork, evJoin;
    cudaStreamCreateWithFlags(&sB, cudaStreamNonBlocking);
    cudaEventCreateWithFlags(&evFork, cudaEventDisableTiming);
    cudaEventCreateWithFlags(&evJoin, cudaEventDisableTiming);

    k_zero  <<<nb_n, TB>>>();
    k_count <<<nb_e, TB>>>(col, E);

    // fork: gemm1 needs only g_cnt; runs concurrently with scan+fill
    cudaEventRecord(evFork, 0);
    cudaStreamWaitEvent(sB, evFork, 0);
    k_gemm1 <<<nb_n, TB, 0, sB>>>(x, W1);     // g_src = dinv * (x @ W1), g_dinv

    k_scan1 <<<nb_s, 1024>>>();
    k_scan2 <<<1, 128>>>(nb_s);
    k_scan3 <<<nb_n, TB>>>();
    k_fill  <<<nb_e, TB>>>(row, col, E);

    cudaEventRecord(evJoin, sB);
    cudaStreamWaitEvent(0, evJoin, 0);        // join before aggregation

    k_agg1  <<<nb_a, TB>>>(b1);               // g_hds (dropout fused)
    k_agg2  <<<nb_a, TB>>>(W2, b2, out);      // out (GEMM fused)
}

// round 4
// speedup vs baseline: 1.2382x; 1.2382x over previous
#include <cuda_runtime.h>

#define NN    100000
#define EEMAX 3200000
#define F1    16
#define F2    40
#define DIN   512

// Scratch (static device globals — no allocation allowed)
__device__ int   g_cnt [NN];        // edge in-degree (without self-loop)
__device__ int   g_off [NN];        // CSR offsets (exclusive scan of cnt)
__device__ int   g_cur [NN];        // fill cursors
__device__ int   g_adj [EEMAX];     // CSR: source node per slot
__device__ int   g_bsum[128];       // scan block sums
__device__ float g_dinv[NN];
__device__ float g_src [NN * F1];   // dinv * (x @ W1)
__device__ float g_hds [NN * F1];   // dinv * dropout(h + b1)

// ---------------------------------------------------------------------------
__global__ void k_count(const int* __restrict__ col, int E) {
    int e = blockIdx.x * blockDim.x + threadIdx.x;
    if (e < E) atomicAdd(&g_cnt[col[e]], 1);
}

// ---------------------------------------------------------------------------
// Two-level exclusive scan of g_cnt -> g_off
__global__ __launch_bounds__(1024) void k_scan1() {
    __shared__ int wsum[32];
    int i = blockIdx.x * 1024 + threadIdx.x;
    int v = (i < NN) ? g_cnt[i] : 0;
    int lane = threadIdx.x & 31, wid = threadIdx.x >> 5;
    int x = v;
#pragma unroll
    for (int d = 1; d < 32; d <<= 1) {
        int y = __shfl_up_sync(0xffffffffu, x, d);
        if (lane >= d) x += y;
    }
    if (lane == 31) wsum[wid] = x;
    __syncthreads();
    if (wid == 0) {
        int w = wsum[lane];
#pragma unroll
        for (int d = 1; d < 32; d <<= 1) {
            int y = __shfl_up_sync(0xffffffffu, w, d);
            if (lane >= d) w += y;
        }
        wsum[lane] = w;
    }
    __syncthreads();
    int incl = x + (wid > 0 ? wsum[wid - 1] : 0);
    if (i < NN) g_off[i] = incl - v;               // block-local exclusive
    if (threadIdx.x == 1023) g_bsum[blockIdx.x] = incl;
}

// parallel exclusive scan of up to 128 block sums (Hillis-Steele)
__global__ void k_scan2(int nb) {
    __shared__ int s[128];
    int t = threadIdx.x;
    int v = (t < nb) ? g_bsum[t] : 0;
    s[t] = v;
    __syncthreads();
#pragma unroll
    for (int d = 1; d < 128; d <<= 1) {
        int y = (t >= d) ? s[t - d] : 0;
        __syncthreads();
        s[t] += y;
        __syncthreads();
    }
    if (t < nb) g_bsum[t] = s[t] - v;              // exclusive
}

__global__ void k_scan3() {
    int i = blockIdx.x * blockDim.x + threadIdx.x;
    if (i < NN) {
        int o = g_off[i] + g_bsum[i >> 10];
        g_off[i] = o;
        g_cur[i] = o;
    }
}

// ---------------------------------------------------------------------------
__global__ void k_fill(const int* __restrict__ row, const int* __restrict__ col, int E) {
    int e = blockIdx.x * blockDim.x + threadIdx.x;
    if (e >= E) return;
    int c = col[e];
    int pos = atomicAdd(&g_cur[c], 1);
    g_adj[pos] = row[e];
}

// ---------------------------------------------------------------------------
// xw = x @ W1 ; dinv = rsqrt(cnt+1) ; g_src = dinv * xw
// Depends ONLY on g_cnt (runs concurrently with scan/fill on a side stream).
__global__ __launch_bounds__(256) void k_gemm1(const float* __restrict__ x,
                                               const float* __restrict__ W1) {
    __shared__ float4 sW[DIN * 4];               // W1[512][16] as float4[512][4]
    const float4* Wv = (const float4*)W1;
    for (int i = threadIdx.x; i < DIN * 4; i += 256) sW[i] = Wv[i];
    __syncthreads();

    int v = blockIdx.x * 256 + threadIdx.x;
    if (v >= NN) return;

    float acc[16];
#pragma unroll
    for (int i = 0; i < 16; ++i) acc[i] = 0.0f;

    const float4* xr = (const float4*)(x + (size_t)v * DIN);
#pragma unroll 4
    for (int j = 0; j < DIN / 4; ++j) {
        float4 xv = xr[j];
#pragma unroll
        for (int u = 0; u < 4; ++u) {
            float xs = (u == 0) ? xv.x : (u == 1) ? xv.y : (u == 2) ? xv.z : xv.w;
            int k = j * 4 + u;
#pragma unroll
            for (int q = 0; q < 4; ++q) {
                float4 w = sW[k * 4 + q];
                acc[q * 4 + 0] += xs * w.x;
                acc[q * 4 + 1] += xs * w.y;
                acc[q * 4 + 2] += xs * w.z;
                acc[q * 4 + 3] += xs * w.w;
            }
        }
    }

    float d = rsqrtf((float)(g_cnt[v] + 1));      // +1 self-loop
    g_dinv[v] = d;
    float4* sv = (float4*)(g_src + (size_t)v * F1);
#pragma unroll
    for (int q = 0; q < 4; ++q)
        sv[q] = make_float4(d * acc[q*4], d * acc[q*4+1], d * acc[q*4+2], d * acc[q*4+3]);
}

// ---------------------------------------------------------------------------
// JAX threefry2x32 (partitionable): key=(0,42), ctr=(0, idx).
// bernoulli(0.5) keep  <=>  MSB(out0 ^ out1) == 0
__device__ __forceinline__ unsigned tf_keep_bits(unsigned idx) {
    const unsigned k0 = 0u, k1 = 42u, k2 = 0u ^ 42u ^ 0x1BD11BDAu;
    unsigned x0 = k0;
    unsigned x1 = idx + k1;
#define TFR(r) { x0 += x1; x1 = (x1 << (r)) | (x1 >> (32 - (r))); x1 ^= x0; }
    TFR(13) TFR(15) TFR(26) TFR(6)   x0 += k1; x1 += k2 + 1u;
    TFR(17) TFR(29) TFR(16) TFR(24)  x0 += k2; x1 += k0 + 2u;
    TFR(13) TFR(15) TFR(26) TFR(6)   x0 += k0; x1 += k1 + 3u;
    TFR(17) TFR(29) TFR(16) TFR(24)  x0 += k1; x1 += k2 + 4u;
    TFR(13) TFR(15) TFR(26) TFR(6)   x0 += k2; x1 += k0 + 5u;
#undef TFR
    return x0 ^ x1;
}

// ---------------------------------------------------------------------------
// 8-deep gather macro body shared by both agg kernels (MLP = 8)
#define AGG_LOOP(SRCP)                                                         \
    float4 acc = SRCP[t * 4 + q];                 /* self-loop term */         \
    {                                                                          \
        int beg = g_off[t], end = beg + g_cnt[t];                              \
        int pos = beg;                                                         \
        for (; pos + 8 <= end; pos += 8) {                                     \
            int r0 = g_adj[pos+0], r1 = g_adj[pos+1];                          \
            int r2 = g_adj[pos+2], r3 = g_adj[pos+3];                          \
            int r4 = g_adj[pos+4], r5 = g_adj[pos+5];                          \
            int r6 = g_adj[pos+6], r7 = g_adj[pos+7];                          \
            float4 s0 = SRCP[r0*4+q], s1 = SRCP[r1*4+q];                       \
            float4 s2 = SRCP[r2*4+q], s3 = SRCP[r3*4+q];                       \
            float4 s4 = SRCP[r4*4+q], s5 = SRCP[r5*4+q];                       \
            float4 s6 = SRCP[r6*4+q], s7 = SRCP[r7*4+q];                       \
            acc.x += ((s0.x+s1.x)+(s2.x+s3.x)) + ((s4.x+s5.x)+(s6.x+s7.x));    \
            acc.y += ((s0.y+s1.y)+(s2.y+s3.y)) + ((s4.y+s5.y)+(s6.y+s7.y));    \
            acc.z += ((s0.z+s1.z)+(s2.z+s3.z)) + ((s4.z+s5.z)+(s6.z+s7.z));    \
            acc.w += ((s0.w+s1.w)+(s2.w+s3.w)) + ((s4.w+s5.w)+(s6.w+s7.w));    \
        }                                                                      \
        for (; pos < end; ++pos) {                                             \
            float4 s = SRCP[g_adj[pos] * 4 + q];                               \
            acc.x += s.x; acc.y += s.y; acc.z += s.z; acc.w += s.w;            \
        }                                                                      \
    }

// Layer-1 aggregation (4 threads per node) + dropout fused.
// g_hds[t] = dinv[t] * dropout( dinv[t]*acc + b1 )
__global__ __launch_bounds__(256) void k_agg1(const float* __restrict__ b1) {
    int tid = blockIdx.x * 64 + (threadIdx.x >> 2);
    int q   = threadIdx.x & 3;
    if (tid >= NN) return;
    int t = tid;

    const float4* src = (const float4*)g_src;
    AGG_LOOP(src)

    float d = g_dinv[t];
    float4 bb = ((const float4*)b1)[q];
    unsigned idx = (unsigned)(t * 16 + q * 4);
    float h0 = d * acc.x + bb.x, h1 = d * acc.y + bb.y;
    float h2 = d * acc.z + bb.z, h3 = d * acc.w + bb.w;
    float o0 = (tf_keep_bits(idx + 0) & 0x80000000u) ? 0.0f : 2.0f * d * h0;
    float o1 = (tf_keep_bits(idx + 1) & 0x80000000u) ? 0.0f : 2.0f * d * h1;
    float o2 = (tf_keep_bits(idx + 2) & 0x80000000u) ? 0.0f : 2.0f * d * h2;
    float o3 = (tf_keep_bits(idx + 3) & 0x80000000u) ? 0.0f : 2.0f * d * h3;
    ((float4*)g_hds)[t * 4 + q] = make_float4(o0, o1, o2, o3);
}

// Layer-2 aggregation + fused (16x40 GEMM + b2); out written directly.
__global__ __launch_bounds__(256) void k_agg2(const float* __restrict__ W2,
                                              const float* __restrict__ b2,
                                              float* __restrict__ out) {
    __shared__ float sW[F1 * F2];
    __shared__ float sb[F2];
    for (int i = threadIdx.x; i < F1 * F2; i += 256) sW[i] = W2[i];
    if (threadIdx.x < F2) sb[threadIdx.x] = b2[threadIdx.x];
    __syncthreads();

    int tid = blockIdx.x * 64 + (threadIdx.x >> 2);
    int q   = threadIdx.x & 3;
    bool valid = tid < NN;
    int t = valid ? tid : NN - 1;

    const float4* src = (const float4*)g_hds;
    AGG_LOOP(src)

    float d = g_dinv[t];
    acc.x *= d; acc.y *= d; acc.z *= d; acc.w *= d;

    // assemble all 16 features into each lane via width-4 shuffles
    float gg[16];
#pragma unroll
    for (int s = 0; s < 4; ++s) {
        gg[s*4+0] = __shfl_sync(0xffffffffu, acc.x, s, 4);
        gg[s*4+1] = __shfl_sync(0xffffffffu, acc.y, s, 4);
        gg[s*4+2] = __shfl_sync(0xffffffffu, acc.z, s, 4);
        gg[s*4+3] = __shfl_sync(0xffffffffu, acc.w, s, 4);
    }

    // each lane computes 10 of the 40 outputs: f in [q*10, q*10+10)
    float o[10];
#pragma unroll
    for (int j = 0; j < 10; ++j) o[j] = sb[q * 10 + j];
#pragma unroll
    for (int k = 0; k < 16; ++k) {
        float gv = gg[k];
        const float* wr = sW + k * F2 + q * 10;
#pragma unroll
        for (int j = 0; j < 10; ++j) o[j] += gv * wr[j];
    }

    if (valid) {
        float* op = out + (size_t)t * F2 + q * 10;
#pragma unroll
        for (int j = 0; j < 10; ++j) op[j] = o[j];
    }
}

// ---------------------------------------------------------------------------
extern "C" void kernel_launch(void* const* d_in, const int* in_sizes, int n_in,
                              void* d_out, int out_size) {
    const float* x  = (const float*)d_in[0];
    const int*   ei = (const int*)  d_in[1];
    const float* W1 = (const float*)d_in[2];
    const float* b1 = (const float*)d_in[3];
    const float* W2 = (const float*)d_in[4];
    const float* b2 = (const float*)d_in[5];
    float* out = (float*)d_out;

    int E = in_sizes[1] / 2;                  // 3,200,000
    if (E > EEMAX) E = EEMAX;
    const int* row = ei;
    const int* col = ei + E;

    const int TB = 256;
    int nb_n = (NN + TB - 1) / TB;
    int nb_e = (E + TB - 1) / TB;
    int nb_s = (NN + 1023) / 1024;            // scan blocks (98)
    int nb_a = (NN + 63) / 64;                // agg blocks (4 thr/node)

    // one-time host-side resources (created on first call, reused by capture)
    static cudaStream_t sB = nullptr;
    static cudaEvent_t evFork = nullptr, evJoin = nullptr;
    static void* cntPtr = nullptr;
    if (!sB) {
        cudaStreamCreateWithFlags(&sB, cudaStreamNonBlocking);
        cudaEventCreateWithFlags(&evFork, cudaEventDisableTiming);
        cudaEventCreateWithFlags(&evJoin, cudaEventDisableTiming);
        cudaGetSymbolAddress(&cntPtr, g_cnt);
    }

    cudaMemsetAsync(cntPtr, 0, NN * sizeof(int), 0);
    k_count <<<nb_e, TB>>>(col, E);

    // fork: gemm1 needs only g_cnt; runs concurrently with scan+fill
    cudaEventRecord(evFork, 0);
    cudaStreamWaitEvent(sB, evFork, 0);
    k_gemm1 <<<nb_n, TB, 0, sB>>>(x, W1);     // g_src = dinv * (x @ W1), g_dinv

    k_scan1 <<<nb_s, 1024>>>();
    k_scan2 <<<1, 128>>>(nb_s);
    k_scan3 <<<nb_n, TB>>>();
    k_fill  <<<nb_e, TB>>>(row, col, E);

    cudaEventRecord(evJoin, sB);
    cudaStreamWaitEvent(0, evJoin, 0);        // join before aggregation

    k_agg1  <<<nb_a, TB>>>(b1);               // g_hds (dropout fused)
    k_agg2  <<<nb_a, TB>>>(W2, b2, out);      // out (GEMM fused)
}

// round 5
// speedup vs baseline: 1.2630x; 1.0200x over previous
#include <cuda_runtime.h>

#define NN    100000
#define EEMAX 3200000
#define F1    16
#define F2    40
#define DIN   512

// Scratch (static device globals — no allocation allowed)
__device__ int   g_cnt [NN];        // edge in-degree (without self-loop)
__device__ int   g_off [NN];        // CSR offsets; after fill: END position
__device__ int   g_adj [EEMAX];     // CSR: source node per slot
__device__ int   g_bsum[128];       // scan block sums
__device__ float g_dinv[NN];
__device__ float g_src [NN * F1];   // x @ W1, then scaled in-place by dinv
__device__ float g_hds [NN * F1];   // dinv * dropout(h + b1)

// ---------------------------------------------------------------------------
// count: 4 edges per thread (int4 load), atomics into g_cnt
__global__ void k_count(const int* __restrict__ col, int E4, int E) {
    int i = blockIdx.x * blockDim.x + threadIdx.x;
    if (i < E4) {
        int4 c = ((const int4*)col)[i];
        atomicAdd(&g_cnt[c.x], 1);
        atomicAdd(&g_cnt[c.y], 1);
        atomicAdd(&g_cnt[c.z], 1);
        atomicAdd(&g_cnt[c.w], 1);
    } else {
        int e = E4 * 4 + (i - E4);               // tail (rarely taken)
        if (e < E) atomicAdd(&g_cnt[col[e]], 1);
    }
}

// ---------------------------------------------------------------------------
// scan1: per-1024-block exclusive scan of g_cnt -> g_off, block sums -> g_bsum
__global__ __launch_bounds__(1024) void k_scan1() {
    __shared__ int wsum[32];
    int i = blockIdx.x * 1024 + threadIdx.x;
    int v = (i < NN) ? g_cnt[i] : 0;
    int lane = threadIdx.x & 31, wid = threadIdx.x >> 5;
    int x = v;
#pragma unroll
    for (int d = 1; d < 32; d <<= 1) {
        int y = __shfl_up_sync(0xffffffffu, x, d);
        if (lane >= d) x += y;
    }
    if (lane == 31) wsum[wid] = x;
    __syncthreads();
    if (wid == 0) {
        int w = wsum[lane];
#pragma unroll
        for (int d = 1; d < 32; d <<= 1) {
            int y = __shfl_up_sync(0xffffffffu, w, d);
            if (lane >= d) w += y;
        }
        wsum[lane] = w;
    }
    __syncthreads();
    int incl = x + (wid > 0 ? wsum[wid - 1] : 0);
    if (i < NN) g_off[i] = incl - v;               // block-local exclusive
    if (threadIdx.x == 1023) g_bsum[blockIdx.x] = incl;
}

// scan23 (merged): add block-sum prefix to g_off; also compute g_dinv.
// Each 256-thread block covers nodes [256b, 256b+256) -> chunk = b/4 constant.
__global__ void k_scan23() {
    __shared__ int sbase;
    int chunk = blockIdx.x >> 2;                   // 1024-chunk index
    if (threadIdx.x < 32) {
        int s = 0;
        for (int j = threadIdx.x; j < chunk; j += 32) s += g_bsum[j];
#pragma unroll
        for (int d = 16; d; d >>= 1) s += __shfl_xor_sync(0xffffffffu, s, d);
        if (threadIdx.x == 0) sbase = s;
    }
    __syncthreads();
    int i = blockIdx.x * 256 + threadIdx.x;
    if (i < NN) {
        g_off[i] += sbase;
        g_dinv[i] = rsqrtf((float)(g_cnt[i] + 1)); // +1 self-loop
    }
}

// ---------------------------------------------------------------------------
// fill: bumps g_off directly (post-fill g_off[t] == end of t's slot range)
__global__ void k_fill(const int* __restrict__ row, const int* __restrict__ col,
                       int E4, int E) {
    int i = blockIdx.x * blockDim.x + threadIdx.x;
    if (i < E4) {
        int4 r = ((const int4*)row)[i];
        int4 c = ((const int4*)col)[i];
        g_adj[atomicAdd(&g_off[c.x], 1)] = r.x;
        g_adj[atomicAdd(&g_off[c.y], 1)] = r.y;
        g_adj[atomicAdd(&g_off[c.z], 1)] = r.z;
        g_adj[atomicAdd(&g_off[c.w], 1)] = r.w;
    } else {
        int e = E4 * 4 + (i - E4);
        if (e < E) g_adj[atomicAdd(&g_off[col[e]], 1)] = row[e];
    }
}

// ---------------------------------------------------------------------------
// gemm1: g_src = x @ W1 (UNSCALED; no dependence on edges -> forks at t=0)
__global__ __launch_bounds__(256) void k_gemm1(const float* __restrict__ x,
                                               const float* __restrict__ W1) {
    __shared__ float4 sW[DIN * 4];               // W1[512][16] as float4[512][4]
    const float4* Wv = (const float4*)W1;
    for (int i = threadIdx.x; i < DIN * 4; i += 256) sW[i] = Wv[i];
    __syncthreads();

    int v = blockIdx.x * 256 + threadIdx.x;
    if (v >= NN) return;

    float acc[16];
#pragma unroll
    for (int i = 0; i < 16; ++i) acc[i] = 0.0f;

    const float4* xr = (const float4*)(x + (size_t)v * DIN);
#pragma unroll 4
    for (int j = 0; j < DIN / 4; ++j) {
        float4 xv = xr[j];
#pragma unroll
        for (int u = 0; u < 4; ++u) {
            float xs = (u == 0) ? xv.x : (u == 1) ? xv.y : (u == 2) ? xv.z : xv.w;
            int k = j * 4 + u;
#pragma unroll
            for (int q = 0; q < 4; ++q) {
                float4 w = sW[k * 4 + q];
                acc[q * 4 + 0] += xs * w.x;
                acc[q * 4 + 1] += xs * w.y;
                acc[q * 4 + 2] += xs * w.z;
                acc[q * 4 + 3] += xs * w.w;
            }
        }
    }

    float4* sv = (float4*)(g_src + (size_t)v * F1);
#pragma unroll
    for (int q = 0; q < 4; ++q)
        sv[q] = make_float4(acc[q*4], acc[q*4+1], acc[q*4+2], acc[q*4+3]);
}

// scale: g_src *= dinv (runs on side stream, concurrent with k_fill)
__global__ void k_scale() {
    int i = blockIdx.x * blockDim.x + threadIdx.x;   // one float4 each
    if (i >= NN * 4) return;
    int v = i >> 2;
    float d = g_dinv[v];
    float4* p = (float4*)g_src + i;
    float4 a = *p;
    *p = make_float4(d * a.x, d * a.y, d * a.z, d * a.w);
}

// ---------------------------------------------------------------------------
// JAX threefry2x32 (partitionable): key=(0,42), ctr=(0, idx).
// bernoulli(0.5) keep  <=>  MSB(out0 ^ out1) == 0
__device__ __forceinline__ unsigned tf_keep_bits(unsigned idx) {
    const unsigned k0 = 0u, k1 = 42u, k2 = 0u ^ 42u ^ 0x1BD11BDAu;
    unsigned x0 = k0;
    unsigned x1 = idx + k1;
#define TFR(r) { x0 += x1; x1 = (x1 << (r)) | (x1 >> (32 - (r))); x1 ^= x0; }
    TFR(13) TFR(15) TFR(26) TFR(6)   x0 += k1; x1 += k2 + 1u;
    TFR(17) TFR(29) TFR(16) TFR(24)  x0 += k2; x1 += k0 + 2u;
    TFR(13) TFR(15) TFR(26) TFR(6)   x0 += k0; x1 += k1 + 3u;
    TFR(17) TFR(29) TFR(16) TFR(24)  x0 += k1; x1 += k2 + 4u;
    TFR(13) TFR(15) TFR(26) TFR(6)   x0 += k2; x1 += k0 + 5u;
#undef TFR
    return x0 ^ x1;
}

// ---------------------------------------------------------------------------
// 8-deep gather loop (MLP = 8); beg/end derived from post-fill g_off
#define AGG_LOOP(SRCP)                                                         \
    float4 acc = SRCP[t * 4 + q];                 /* self-loop term */         \
    {                                                                          \
        int end = g_off[t], beg = end - g_cnt[t];                              \
        int pos = beg;                                                         \
        for (; pos + 8 <= end; pos += 8) {                                     \
            int r0 = g_adj[pos+0], r1 = g_adj[pos+1];                          \
            int r2 = g_adj[pos+2], r3 = g_adj[pos+3];                          \
            int r4 = g_adj[pos+4], r5 = g_adj[pos+5];                          \
            int r6 = g_adj[pos+6], r7 = g_adj[pos+7];                          \
            float4 s0 = SRCP[r0*4+q], s1 = SRCP[r1*4+q];                       \
            float4 s2 = SRCP[r2*4+q], s3 = SRCP[r3*4+q];                       \
            float4 s4 = SRCP[r4*4+q], s5 = SRCP[r5*4+q];                       \
            float4 s6 = SRCP[r6*4+q], s7 = SRCP[r7*4+q];                       \
            acc.x += ((s0.x+s1.x)+(s2.x+s3.x)) + ((s4.x+s5.x)+(s6.x+s7.x));    \
            acc.y += ((s0.y+s1.y)+(s2.y+s3.y)) + ((s4.y+s5.y)+(s6.y+s7.y));    \
            acc.z += ((s0.z+s1.z)+(s2.z+s3.z)) + ((s4.z+s5.z)+(s6.z+s7.z));    \
            acc.w += ((s0.w+s1.w)+(s2.w+s3.w)) + ((s4.w+s5.w)+(s6.w+s7.w));    \
        }                                                                      \
        for (; pos < end; ++pos) {                                             \
            float4 s = SRCP[g_adj[pos] * 4 + q];                               \
            acc.x += s.x; acc.y += s.y; acc.z += s.z; acc.w += s.w;            \
        }                                                                      \
    }

// Layer-1 aggregation (4 threads per node) + dropout fused.
__global__ __launch_bounds__(256) void k_agg1(const float* __restrict__ b1) {
    int tid = blockIdx.x * 64 + (threadIdx.x >> 2);
    int q   = threadIdx.x & 3;
    if (tid >= NN) return;
    int t = tid;

    const float4* src = (const float4*)g_src;
    AGG_LOOP(src)

    float d = g_dinv[t];
    float4 bb = ((const float4*)b1)[q];
    unsigned idx = (unsigned)(t * 16 + q * 4);
    float h0 = d * acc.x + bb.x, h1 = d * acc.y + bb.y;
    float h2 = d * acc.z + bb.z, h3 = d * acc.w + bb.w;
    float o0 = (tf_keep_bits(idx + 0) & 0x80000000u) ? 0.0f : 2.0f * d * h0;
    float o1 = (tf_keep_bits(idx + 1) & 0x80000000u) ? 0.0f : 2.0f * d * h1;
    float o2 = (tf_keep_bits(idx + 2) & 0x80000000u) ? 0.0f : 2.0f * d * h2;
    float o3 = (tf_keep_bits(idx + 3) & 0x80000000u) ? 0.0f : 2.0f * d * h3;
    ((float4*)g_hds)[t * 4 + q] = make_float4(o0, o1, o2, o3);
}

// Layer-2 aggregation + fused (16x40 GEMM + b2); out written directly.
__global__ __launch_bounds__(256) void k_agg2(const float* __restrict__ W2,
                                              const float* __restrict__ b2,
                                              float* __restrict__ out) {
    __shared__ float sW[F1 * F2];
    __shared__ float sb[F2];
    for (int i = threadIdx.x; i < F1 * F2; i += 256) sW[i] = W2[i];
    if (threadIdx.x < F2) sb[threadIdx.x] = b2[threadIdx.x];
    __syncthreads();

    int tid = blockIdx.x * 64 + (threadIdx.x >> 2);
    int q   = threadIdx.x & 3;
    bool valid = tid < NN;
    int t = valid ? tid : NN - 1;

    const float4* src = (const float4*)g_hds;
    AGG_LOOP(src)

    float d = g_dinv[t];
    acc.x *= d; acc.y *= d; acc.z *= d; acc.w *= d;

    float gg[16];
#pragma unroll
    for (int s = 0; s < 4; ++s) {
        gg[s*4+0] = __shfl_sync(0xffffffffu, acc.x, s, 4);
        gg[s*4+1] = __shfl_sync(0xffffffffu, acc.y, s, 4);
        gg[s*4+2] = __shfl_sync(0xffffffffu, acc.z, s, 4);
        gg[s*4+3] = __shfl_sync(0xffffffffu, acc.w, s, 4);
    }

    float o[10];
#pragma unroll
    for (int j = 0; j < 10; ++j) o[j] = sb[q * 10 + j];
#pragma unroll
    for (int k = 0; k < 16; ++k) {
        float gv = gg[k];
        const float* wr = sW + k * F2 + q * 10;
#pragma unroll
        for (int j = 0; j < 10; ++j) o[j] += gv * wr[j];
    }

    if (valid) {
        float* op = out + (size_t)t * F2 + q * 10;
#pragma unroll
        for (int j = 0; j < 10; ++j) op[j] = o[j];
    }
}

// ---------------------------------------------------------------------------
extern "C" void kernel_launch(void* const* d_in, const int* in_sizes, int n_in,
                              void* d_out, int out_size) {
    const float* x  = (const float*)d_in[0];
    const int*   ei = (const int*)  d_in[1];
    const float* W1 = (const float*)d_in[2];
    const float* b1 = (const float*)d_in[3];
    const float* W2 = (const float*)d_in[4];
    const float* b2 = (const float*)d_in[5];
    float* out = (float*)d_out;

    int E = in_sizes[1] / 2;                  // 3,200,000
    if (E > EEMAX) E = EEMAX;
    const int* row = ei;
    const int* col = ei + E;
    int E4 = E / 4;

    const int TB = 256;
    int nb_n  = (NN + TB - 1) / TB;
    int nb_e4 = (E4 + (E - E4 * 4) + TB - 1) / TB;
    int nb_s  = (NN + 1023) / 1024;           // scan blocks (98)
    int nb_a  = (NN + 63) / 64;               // agg blocks (4 thr/node)
    int nb_sc = (NN * 4 + TB - 1) / TB;       // scale blocks

    // one-time host-side resources (created on first call, reused by capture)
    static cudaStream_t sB = nullptr;
    static cudaEvent_t evStart = nullptr, evScan = nullptr, evScale = nullptr;
    static void* cntPtr = nullptr;
    if (!sB) {
        cudaStreamCreateWithFlags(&sB, cudaStreamNonBlocking);
        cudaEventCreateWithFlags(&evStart, cudaEventDisableTiming);
        cudaEventCreateWithFlags(&evScan,  cudaEventDisableTiming);
        cudaEventCreateWithFlags(&evScale, cudaEventDisableTiming);
        cudaGetSymbolAddress(&cntPtr, g_cnt);
    }

    // fork side stream at t=0: gemm1 is pure input -> runs under entire build
    cudaEventRecord(evStart, 0);
    cudaStreamWaitEvent(sB, evStart, 0);
    k_gemm1 <<<nb_n, TB, 0, sB>>>(x, W1);     // g_src = x @ W1 (unscaled)

    cudaMemsetAsync(cntPtr, 0, NN * sizeof(int), 0);
    k_count <<<nb_e4, TB>>>(col, E4, E);
    k_scan1 <<<nb_s, 1024>>>();
    k_scan23<<<nb_n, TB>>>();                 // off += prefix; dinv = rsqrt(cnt+1)

    cudaEventRecord(evScan, 0);               // dinv ready
    cudaStreamWaitEvent(sB, evScan, 0);
    k_scale <<<nb_sc, TB, 0, sB>>>();         // g_src *= dinv (|| with fill)
    cudaEventRecord(evScale, sB);

    k_fill  <<<nb_e4, TB>>>(row, col, E4, E); // g_adj; g_off -> end positions

    cudaStreamWaitEvent(0, evScale, 0);       // join before aggregation
    k_agg1  <<<nb_a, TB>>>(b1);               // g_hds (dropout fused)
    k_agg2  <<<nb_a, TB>>>(W2, b2, out);      // out (GEMM fused)
}